// round 5
// baseline (speedup 1.0000x reference)
#include <cuda_runtime.h>

// x [32, 512, 512] f32 -> pad 128 -> [32,768,768] -> NN upsample x4 -> [32,3072,3072] f32.
// out[b, i, j] = x[b, i/4 - 128, j/4 - 128] if in-bounds else 0.
//
// One thread = 64B-wide output strip (16 floats = 4 source cols) x 4 output rows:
//   1 LDG.128 (L2-resident input) + 8 STG.256 (st.global.cs.v8.f32).
// Per warp, each output row gets 2048B of contiguous stores. Store traffic
// = 1.21 GB (minimum). Source row/col shared across the 4x16 output tile.

#define B        32
#define HW       512
#define OW       3072         // (512 + 2*128) * 4
#define OW4      768          // float4 groups per output row
#define GRP      192          // 64B groups per output row (768*16B / 64B)
#define SRCROWS  768          // padded source rows
#define TILES_PER_B (SRCROWS * GRP)       // 147456
#define NTILES   (B * TILES_PER_B)        // 4718592

__device__ __forceinline__ void st256_cs(float4* p, float a, float b) {
    asm volatile(
        "st.global.cs.v8.f32 [%0], {%1,%2,%3,%4,%5,%6,%7,%8};"
        :: "l"(p), "f"(a), "f"(a), "f"(a), "f"(a),
           "f"(b), "f"(b), "f"(b), "f"(b)
        : "memory");
}

__global__ __launch_bounds__(256) void scale_layer_kernel(
    const float* __restrict__ x, float4* __restrict__ out)
{
    unsigned idx = blockIdx.x * 256u + threadIdx.x;

    unsigned b     = idx / (unsigned)TILES_PER_B;
    unsigned rem   = idx - b * (unsigned)TILES_PER_B;
    unsigned orow4 = rem / (unsigned)GRP;          // padded source row [0,768)
    unsigned g     = rem - orow4 * (unsigned)GRP;  // 64B col group [0,192)

    int r = (int)orow4 - 128;        // source row
    int c = (int)(g * 4u) - 128;     // first of four source cols (multiple of 4)

    float4 s = make_float4(0.f, 0.f, 0.f, 0.f);
    if ((unsigned)r < (unsigned)HW && (unsigned)c < (unsigned)HW) {
        // c in-bounds (and multiple of 4) implies c..c+3 in-bounds
        s = *(const float4*)(x + (size_t)b * (HW * HW)
                               + (unsigned)r * HW + (unsigned)c);
    }

    // Output base: row orow4*4, float4 column 4g (32B-aligned v8 stores).
    float4* p = out + ((size_t)b * OW + (size_t)orow4 * 4u) * OW4 + 4u * g;
    st256_cs(p,               s.x, s.y);
    st256_cs(p + 2,           s.z, s.w);
    st256_cs(p + OW4,         s.x, s.y);
    st256_cs(p + OW4 + 2,     s.z, s.w);
    st256_cs(p + 2 * OW4,     s.x, s.y);
    st256_cs(p + 2 * OW4 + 2, s.z, s.w);
    st256_cs(p + 3 * OW4,     s.x, s.y);
    st256_cs(p + 3 * OW4 + 2, s.z, s.w);
}

extern "C" void kernel_launch(void* const* d_in, const int* in_sizes, int n_in,
                              void* d_out, int out_size)
{
    const float* x = (const float*)d_in[0];
    float4* out = (float4*)d_out;
    // NTILES / 256 = 18432 blocks exactly
    scale_layer_kernel<<<NTILES / 256, 256>>>(x, out);
}